// round 1
// baseline (speedup 1.0000x reference)
#include <cuda_runtime.h>
#include <math_constants.h>

// Problem constants (fixed by dataset: B=8, E=100; N,F derived at launch)
#define BB 8
#define EE 100
#define E4 25        // float4 per embedding row (100 floats)
#define FPAD 4096    // padded F/N for scratch arrays

// Main-kernel tiling
#define TX 16
#define TYV 16
#define MN 7         // n rows per thread  -> NT = 112
#define MF 4         // f cols per thread  -> FT = 64
#define NT (TX*MN)
#define FT (TYV*MF)

#define ROWB 432     // bytes per smem embedding row: 27 float4 (25 used + pad)
                     // stride 108 words -> conflict-free LDS.128 (gcd(12,32)=4 pattern)
#define ENT_BYTES (NT*ROWB)              // 48384
#define FACT_BYTES (FT*ROWB)             // 27648
#define A_BYTES (BB*FT*4)                // 2048
#define SMEM_TOTAL (ENT_BYTES + 2*FACT_BYTES + 2*A_BYTES)   // 107776 B

// Scratch (no cudaMalloc allowed)
__device__ float g_A[2][BB][FPAD];     // A_sp (z=0), A_po (z=1); INF-padded for f>=F
__device__ float g_e2[FPAD];
__device__ float g_min[2][BB][FPAD];   // running min of (A - 2*dot), init +INF

__device__ __forceinline__ unsigned long long fma2(unsigned long long a,
                                                   unsigned long long b,
                                                   unsigned long long c) {
  unsigned long long d;
  asm("fma.rn.f32x2 %0, %1, %2, %3;" : "=l"(d) : "l"(a), "l"(b), "l"(c));
  return d;
}

// Order-correct float atomic min via int min / uint max trick (no NaNs here).
__device__ __forceinline__ void atomicMinF(float* addr, float v) {
  if (v >= 0.0f) atomicMin((int*)addr, __float_as_int(v));
  else           atomicMax((unsigned int*)addr, __float_as_uint(v));
}

// ---------------------------------------------------------------------------
__global__ void k_init() {
  int i = blockIdx.x * blockDim.x + threadIdx.x;   // exactly 2*BB*FPAD threads
  ((float*)g_min)[i] = CUDART_INF_F;
}

// A_sp[b,f] = ||rel-fr||^2 + ||arg1-fa1||^2 + ||fa2||^2   (pairs with dot over fa2)
// A_po[b,f] = ||rel-fr||^2 + ||arg2-fa2||^2 + ||fa1||^2   (pairs with dot over fa1)
__global__ void k_prepA(const float* __restrict__ rel, const float* __restrict__ a1,
                        const float* __restrict__ a2, const float* __restrict__ fr,
                        const float* __restrict__ f1, const float* __restrict__ f2,
                        int F) {
  int f = blockIdx.x * blockDim.x + threadIdx.x;
  if (f >= FPAD) return;
  if (f >= F) {
    for (int b = 0; b < BB; b++) {
      g_A[0][b][f] = CUDART_INF_F;
      g_A[1][b][f] = CUDART_INF_F;
    }
    return;
  }
  float srel[BB], s11[BB], s22[BB];
#pragma unroll
  for (int b = 0; b < BB; b++) { srel[b] = 0.f; s11[b] = 0.f; s22[b] = 0.f; }
  float n1 = 0.f, n2 = 0.f;
  for (int e = 0; e < EE; e++) {
    float vr = fr[f * EE + e], v1 = f1[f * EE + e], v2 = f2[f * EE + e];
    n1 += v1 * v1;
    n2 += v2 * v2;
#pragma unroll
    for (int b = 0; b < BB; b++) {
      float t = rel[b * EE + e] - vr; srel[b] += t * t;
      t = a1[b * EE + e] - v1;        s11[b]  += t * t;
      t = a2[b * EE + e] - v2;        s22[b]  += t * t;
    }
  }
#pragma unroll
  for (int b = 0; b < BB; b++) {
    g_A[0][b][f] = srel[b] + s11[b] + n2;
    g_A[1][b][f] = srel[b] + s22[b] + n1;
  }
}

__global__ void k_e2(const float4* __restrict__ ent, int N) {
  int n = blockIdx.x * blockDim.x + threadIdx.x;
  if (n >= N) return;
  float s = 0.f;
#pragma unroll
  for (int q = 0; q < E4; q++) {
    float4 v = ent[n * E4 + q];
    s += v.x * v.x + v.y * v.y + v.z * v.z + v.w * v.w;
  }
  g_e2[n] = s;
}

// ---------------------------------------------------------------------------
// Main fused dot + min-plus kernel.
// grid = (ceil(N/112), 4 f-splits, 2 problems {sp: fa2, po: fa1})
__global__ __launch_bounds__(256, 1) void k_main(const float4* __restrict__ ent,
                                                 const float4* __restrict__ fa1,
                                                 const float4* __restrict__ fa2,
                                                 int N, int F) {
  extern __shared__ char sm[];
  const int tid = threadIdx.x;
  const int tx = tid & 15;
  const int ty = tid >> 4;
  const int z = blockIdx.z;
  const int n0 = blockIdx.x * NT;
  const int FRANGE = (F + 3) >> 2;                 // 1000 for F=4000
  const int fbase = blockIdx.y * FRANGE;
  const int NCH = (FRANGE + FT - 1) / FT;          // 16
  const float4* fac = (z == 0) ? fa2 : fa1;
  const float* Abase = &g_A[z][0][0];

  char* smEnt = sm;
  char* smFact0 = sm + ENT_BYTES;
  char* smA0 = sm + ENT_BYTES + 2 * FACT_BYTES;

  // cp.async stage for fact chunk c into buffer buf (also stages the A slice)
  auto issue = [&](int c, int buf) {
    const int f0 = fbase + c * FT;
    char* dF = smFact0 + buf * FACT_BYTES;
    for (int idx = tid; idx < FT * E4; idx += 256) {
      int r = idx / E4, q = idx - r * E4;
      int f = f0 + r; if (f > F - 1) f = F - 1;
      const float4* src = &fac[f * E4 + q];
      unsigned dst = (unsigned)__cvta_generic_to_shared(dF + r * ROWB + q * 16);
      asm volatile("cp.async.cg.shared.global [%0], [%1], 16;" :: "r"(dst), "l"(src));
    }
    char* dA = smA0 + buf * A_BYTES;
    for (int idx = tid; idx < BB * (FT / 4); idx += 256) {   // 128 granules
      int b = idx >> 4, q = idx & 15;
      const float* src = Abase + b * FPAD + f0 + q * 4;
      unsigned dst = (unsigned)__cvta_generic_to_shared(dA + (b * FT + q * 4) * 4);
      asm volatile("cp.async.cg.shared.global [%0], [%1], 16;" :: "r"(dst), "l"(src));
    }
    asm volatile("cp.async.commit_group;");
  };

  issue(0, 0);

  // Load entity tile, scaled by -2 so acc directly accumulates -2*dot
  for (int idx = tid; idx < NT * E4; idx += 256) {
    int r = idx / E4, q = idx - r * E4;
    int n = n0 + r; if (n > N - 1) n = N - 1;
    float4 v = ent[n * E4 + q];
    v.x *= -2.f; v.y *= -2.f; v.z *= -2.f; v.w *= -2.f;
    *(float4*)(smEnt + r * ROWB + q * 16) = v;
  }

  float rm[BB][MN];
#pragma unroll
  for (int b = 0; b < BB; b++)
#pragma unroll
    for (int i = 0; i < MN; i++) rm[b][i] = CUDART_INF_F;

  for (int c = 0; c < NCH; c++) {
    int buf = c & 1;
    if (c + 1 < NCH) {
      issue(c + 1, buf ^ 1);
      asm volatile("cp.async.wait_group 1;");
    } else {
      asm volatile("cp.async.wait_group 0;");
    }
    __syncthreads();

    unsigned long long acc[MN][MF];
#pragma unroll
    for (int i = 0; i < MN; i++)
#pragma unroll
      for (int j = 0; j < MF; j++) acc[i][j] = 0ull;

    const char* eBase = smEnt + tx * ROWB;
    const char* fBase = smFact0 + buf * FACT_BYTES + ty * ROWB;
#pragma unroll 5
    for (int q = 0; q < E4; q++) {
      ulonglong2 fv[MF];
#pragma unroll
      for (int j = 0; j < MF; j++)
        fv[j] = *(const ulonglong2*)(fBase + j * (16 * ROWB) + q * 16);
#pragma unroll
      for (int i = 0; i < MN; i++) {
        ulonglong2 ev = *(const ulonglong2*)(eBase + i * (16 * ROWB) + q * 16);
#pragma unroll
        for (int j = 0; j < MF; j++) {
          acc[i][j] = fma2(ev.x, fv[j].x, acc[i][j]);
          acc[i][j] = fma2(ev.y, fv[j].y, acc[i][j]);
        }
      }
    }

    // horizontal add (acc already holds -2*dot pairs), then min-plus over b
    float ds[MN][MF];
#pragma unroll
    for (int i = 0; i < MN; i++)
#pragma unroll
      for (int j = 0; j < MF; j++) {
        float lo = __uint_as_float((unsigned)acc[i][j]);
        float hi = __uint_as_float((unsigned)(acc[i][j] >> 32));
        ds[i][j] = lo + hi;
      }
    const float* As = (const float*)(smA0 + buf * A_BYTES);
#pragma unroll
    for (int b = 0; b < BB; b++) {
      float ab[MF];
#pragma unroll
      for (int j = 0; j < MF; j++) ab[j] = As[b * FT + ty + 16 * j];
#pragma unroll
      for (int i = 0; i < MN; i++)
#pragma unroll
        for (int j = 0; j < MF; j++)
          rm[b][i] = fminf(rm[b][i], ab[j] + ds[i][j]);
    }
    __syncthreads();
  }

  // cross-ty reduction in smem (reuse tile memory), then one atomic per (b,n)
  float* red = (float*)sm;   // needs 16*8*112*4 = 57344 B <= SMEM_TOTAL
#pragma unroll
  for (int b = 0; b < BB; b++)
#pragma unroll
    for (int i = 0; i < MN; i++)
      red[(ty * BB + b) * NT + tx + 16 * i] = rm[b][i];
  __syncthreads();
  for (int o = tid; o < BB * NT; o += 256) {
    int b = o / NT, nl = o - b * NT;
    float m = CUDART_INF_F;
#pragma unroll
    for (int t = 0; t < TYV; t++) m = fminf(m, red[(t * BB + b) * NT + nl]);
    int n = n0 + nl;
    if (n < N) atomicMinF(&g_min[z][b][n], m);
  }
}

// ---------------------------------------------------------------------------
__global__ void k_final(float* __restrict__ out, int N) {
  int idx = blockIdx.x * blockDim.x + threadIdx.x;
  if (idx >= 2 * BB * N) return;
  int z = idx / (BB * N);
  int r = idx - z * (BB * N);
  int b = r / N;
  int n = r - b * N;
  float d2 = g_min[z][b][n] + g_e2[n];
  d2 = fmaxf(d2, 0.f);
  out[idx] = expf(-0.5f * d2);
}

// ---------------------------------------------------------------------------
extern "C" void kernel_launch(void* const* d_in, const int* in_sizes, int n_in,
                              void* d_out, int out_size) {
  const float* rel = (const float*)d_in[0];
  const float* a1  = (const float*)d_in[1];
  const float* a2  = (const float*)d_in[2];
  const float* fr  = (const float*)d_in[3];
  const float* f1  = (const float*)d_in[4];
  const float* f2  = (const float*)d_in[5];
  const float* ent = (const float*)d_in[6];
  int F = in_sizes[3] / EE;
  int N = in_sizes[6] / EE;

  cudaFuncSetAttribute(k_main, cudaFuncAttributeMaxDynamicSharedMemorySize,
                       SMEM_TOTAL);

  k_init<<<(2 * BB * FPAD) / 256, 256>>>();
  k_prepA<<<FPAD / 128, 128>>>(rel, a1, a2, fr, f1, f2, F);
  k_e2<<<(N + 127) / 128, 128>>>((const float4*)ent, N);

  dim3 grid((N + NT - 1) / NT, 4, 2);   // 37 x 4 x 2 = 296 blocks = 2 even waves
  k_main<<<grid, 256, SMEM_TOTAL>>>((const float4*)ent, (const float4*)f1,
                                    (const float4*)f2, N, F);

  int tot = 2 * BB * N;
  k_final<<<(tot + 255) / 256, 256>>>((float*)d_out, N);
}

// round 4
// speedup vs baseline: 2.6683x; 2.6683x over previous
#include <cuda_runtime.h>
#include <cuda_bf16.h>
#include <math_constants.h>
#include <cstdint>

#define BB 8
#define EE 100
#define FPAD 4096
#define NTILE 128         // n rows per CTA tile
#define FCH 128           // f cols per chunk
#define FSPLIT 2
#define KROW 128          // bf16 per stored row (256B), zeros past 99
#define NKS 7             // 7 x k16 = 112 (zeros past 99 contribute 0)

// smem layout
#define TILE_HALF 16384                 // 128 rows x 128B (one 64-wide bf16 half)
#define SM_ENT 0                        // 2 halves
#define SM_FACT (2*TILE_HALF)           // 2 buffers x 2 halves
#define FACT_BUF (2*TILE_HALF)
#define SM_A (SM_FACT + 2*FACT_BUF)     // 2 buffers of [128 f][8 b] fp32
#define A_BUF 4096
#define SM_TOTAL (SM_A + 2*A_BUF)       // 106496 B

// ---- device scratch ----
__device__ float g_At[2][FPAD][BB];            // A transposed, +INF for f>=F
__device__ float g_e2[FPAD];
__device__ float g_min[2][BB][FPAD];
__device__ __nv_bfloat16 g_eb[FPAD * KROW];    // -2*ent
__device__ __nv_bfloat16 g_fb[2][FPAD * KROW]; // [0]=fa2(sp), [1]=fa1(po)

// ---- helpers ----
__device__ __forceinline__ unsigned swz(unsigned b) { return b ^ ((b >> 3) & 0x70); }
__device__ __forceinline__ unsigned smem_u32(const void* p) {
  return (unsigned)__cvta_generic_to_shared(p);
}
__device__ __forceinline__ void cp16(unsigned dst, const void* src) {
  asm volatile("cp.async.cg.shared.global [%0], [%1], 16;" :: "r"(dst), "l"(src));
}
__device__ __forceinline__ void ldmx4(uint32_t* r, unsigned addr) {
  asm volatile("ldmatrix.sync.aligned.m8n8.x4.shared.b16 {%0,%1,%2,%3}, [%4];"
               : "=r"(r[0]), "=r"(r[1]), "=r"(r[2]), "=r"(r[3]) : "r"(addr));
}
__device__ __forceinline__ void mma16816(float* c, const uint32_t* a,
                                         uint32_t b0, uint32_t b1) {
  asm volatile("mma.sync.aligned.m16n8k16.row.col.f32.bf16.bf16.f32 "
               "{%0,%1,%2,%3}, {%4,%5,%6,%7}, {%8,%9}, {%0,%1,%2,%3};"
               : "+f"(c[0]), "+f"(c[1]), "+f"(c[2]), "+f"(c[3])
               : "r"(a[0]), "r"(a[1]), "r"(a[2]), "r"(a[3]), "r"(b0), "r"(b1));
}
__device__ __forceinline__ void atomicMinF(float* addr, float v) {
  if (v >= 0.0f) atomicMin((int*)addr, __float_as_int(v));
  else           atomicMax((unsigned int*)addr, __float_as_uint(v));
}

// ---- prep kernels ----
__global__ void k_init() {
  int i = blockIdx.x * blockDim.x + threadIdx.x;
  ((float*)g_min)[i] = CUDART_INF_F;
}

__global__ void k_conv(const float* __restrict__ ent, const float* __restrict__ f2,
                       const float* __restrict__ f1, int N, int F) {
  int sel = blockIdx.y;
  int idx = blockIdx.x * 256 + threadIdx.x;
  int r = idx >> 7, j = idx & 127;
  const float* src = (sel == 0) ? ent : (sel == 1 ? f2 : f1);
  int rows = (sel == 0) ? N : F;
  float scale = (sel == 0) ? -2.0f : 1.0f;
  float v = (r < rows && j < EE) ? scale * src[r * EE + j] : 0.f;
  __nv_bfloat16* dst = (sel == 0) ? g_eb : g_fb[sel - 1];
  dst[idx] = __float2bfloat16(v);
}

__global__ void k_prepA(const float* __restrict__ rel, const float* __restrict__ a1,
                        const float* __restrict__ a2, const float* __restrict__ fr,
                        const float* __restrict__ f1, const float* __restrict__ f2,
                        int F) {
  __shared__ __align__(16) float q[3][BB][EE];
  int tid = threadIdx.x;  // 128
  for (int i = tid; i < 3 * BB * EE; i += 128) {
    int t = i / (BB * EE), rem = i - t * (BB * EE);
    int b = rem / EE, e = rem - b * EE;
    const float* s = (t == 0) ? rel : (t == 1 ? a1 : a2);
    q[t][b][e] = s[b * EE + e];
  }
  __syncthreads();
  int f = blockIdx.x * 128 + tid;
  if (f >= F) {
#pragma unroll
    for (int b = 0; b < BB; b++) {
      g_At[0][f][b] = CUDART_INF_F;
      g_At[1][f][b] = CUDART_INF_F;
    }
    return;
  }
  const float4* pr = (const float4*)(fr + (size_t)f * EE);
  const float4* p1 = (const float4*)(f1 + (size_t)f * EE);
  const float4* p2 = (const float4*)(f2 + (size_t)f * EE);
  float sr[BB], s1v[BB], s2v[BB];
#pragma unroll
  for (int b = 0; b < BB; b++) { sr[b] = 0.f; s1v[b] = 0.f; s2v[b] = 0.f; }
  float n1 = 0.f, n2 = 0.f;
  for (int e4 = 0; e4 < EE / 4; e4++) {
    float4 vr = pr[e4], v1 = p1[e4], v2 = p2[e4];
    n1 += v1.x * v1.x + v1.y * v1.y + v1.z * v1.z + v1.w * v1.w;
    n2 += v2.x * v2.x + v2.y * v2.y + v2.z * v2.z + v2.w * v2.w;
#pragma unroll
    for (int b = 0; b < BB; b++) {
      float4 qr = *(const float4*)&q[0][b][e4 * 4];
      float4 q1 = *(const float4*)&q[1][b][e4 * 4];
      float4 q2 = *(const float4*)&q[2][b][e4 * 4];
      float t;
      t = qr.x - vr.x; sr[b] += t * t;  t = qr.y - vr.y; sr[b] += t * t;
      t = qr.z - vr.z; sr[b] += t * t;  t = qr.w - vr.w; sr[b] += t * t;
      t = q1.x - v1.x; s1v[b] += t * t; t = q1.y - v1.y; s1v[b] += t * t;
      t = q1.z - v1.z; s1v[b] += t * t; t = q1.w - v1.w; s1v[b] += t * t;
      t = q2.x - v2.x; s2v[b] += t * t; t = q2.y - v2.y; s2v[b] += t * t;
      t = q2.z - v2.z; s2v[b] += t * t; t = q2.w - v2.w; s2v[b] += t * t;
    }
  }
#pragma unroll
  for (int b = 0; b < BB; b++) {
    g_At[0][f][b] = sr[b] + s1v[b] + n2;   // sp pairs with fa2 dot
    g_At[1][f][b] = sr[b] + s2v[b] + n1;   // po pairs with fa1 dot
  }
}

__global__ void k_e2(const float4* __restrict__ ent, int N) {
  int n = blockIdx.x * blockDim.x + threadIdx.x;
  if (n >= N) return;
  float s = 0.f;
#pragma unroll
  for (int qq = 0; qq < EE / 4; qq++) {
    float4 v = ent[n * (EE / 4) + qq];
    s += v.x * v.x + v.y * v.y + v.z * v.z + v.w * v.w;
  }
  g_e2[n] = s;
}

// ---- main HMMA kernel ----
__global__ __launch_bounds__(256, 1) void k_main(int N) {
  extern __shared__ char sm[];
  const int tid = threadIdx.x;
  const int wid = tid >> 5;
  const int lane = tid & 31;
  const unsigned smb = smem_u32(sm);
  const int z = blockIdx.z;
  const int n0 = blockIdx.x * NTILE;
  const int f0base = blockIdx.y * (FPAD / FSPLIT);
  const int NCH = (FPAD / FSPLIT) / FCH;   // 16
  const __nv_bfloat16* fb = g_fb[z];

  const int wn = wid & 3, wf = wid >> 2;   // warp grid 4(n) x 2(f)
  const int g = lane >> 2, tl = lane & 3;
  const int lrow = lane & 7, mm = lane >> 3;

  // ldmatrix per-lane bases
  const int xoff = 16 * (mm >> 1);
  unsigned aRowOff[2], aXor[2];
#pragma unroll
  for (int mi = 0; mi < 2; mi++) {
    int r = 32 * wn + 16 * mi + lrow + 8 * (mm & 1);
    aRowOff[mi] = r * 128;
    aXor[mi] = (r & 7) * 16;
  }
  unsigned bRowOff[4], bXor[4];
#pragma unroll
  for (int njp = 0; njp < 4; njp++) {
    int r = 64 * wf + 16 * njp + lrow + 8 * (mm & 1);
    bRowOff[njp] = r * 128;
    bXor[njp] = (r & 7) * 16;
  }

  // staging helpers
  auto stage_tile = [&](const __nv_bfloat16* srcRows, unsigned dstBase) {
    const char* sb = (const char*)srcRows;
#pragma unroll
    for (int i = 0; i < 8; i++) {
      int idx = tid + i * 256;
      int half = idx >> 10;
      int rem = idx & 1023;
      int r = rem >> 3, gg = rem & 7;
      cp16(dstBase + half * TILE_HALF + swz(r * 128 + gg * 16),
           sb + (size_t)r * 256 + half * 128 + gg * 16);
    }
  };
  auto stage_fact = [&](int c, int bi) {
    stage_tile(fb + (size_t)(f0base + c * FCH) * KROW, smb + SM_FACT + bi * FACT_BUF);
  };
  auto stage_A = [&](int c, int bi) {
    int f0 = f0base + c * FCH;
    int r = tid >> 1, h = tid & 1;
    cp16(smb + SM_A + bi * A_BUF + tid * 16, &g_At[z][f0 + r][h * 4]);
  };

  stage_tile(g_eb + (size_t)n0 * KROW, smb + SM_ENT);
  stage_fact(0, 0);
  stage_A(0, 0);
  asm volatile("cp.async.commit_group;");

  float rm[2][2][BB];   // [mi][rowhalf][b]
#pragma unroll
  for (int mi = 0; mi < 2; mi++)
#pragma unroll
    for (int h = 0; h < 2; h++)
#pragma unroll
      for (int b = 0; b < BB; b++) rm[mi][h][b] = CUDART_INF_F;

  for (int c = 0; c < NCH; c++) {
    const int buf = c & 1;
    asm volatile("cp.async.wait_group 0;");
    __syncthreads();
    if (c + 1 < NCH) {
      stage_fact(c + 1, buf ^ 1);
      stage_A(c + 1, buf ^ 1);
      asm volatile("cp.async.commit_group;");
    }

    float acc[2][8][4];
#pragma unroll
    for (int mi = 0; mi < 2; mi++)
#pragma unroll
      for (int nj = 0; nj < 8; nj++)
#pragma unroll
        for (int k = 0; k < 4; k++) acc[mi][nj][k] = 0.f;

    const unsigned fBase = smb + SM_FACT + buf * FACT_BUF;
#pragma unroll
    for (int ks = 0; ks < NKS; ks++) {
      const int half = (ks >= 4);
      const int kb = (ks - (half ? 4 : 0)) * 32 + xoff;
      const unsigned aB = smb + SM_ENT + half * TILE_HALF;
      const unsigned bB = fBase + half * TILE_HALF;
      uint32_t af[2][4];
#pragma unroll
      for (int mi = 0; mi < 2; mi++)
        ldmx4(af[mi], aB + aRowOff[mi] + ((unsigned)kb ^ aXor[mi]));
      uint32_t bf[4][4];
#pragma unroll
      for (int njp = 0; njp < 4; njp++)
        ldmx4(bf[njp], bB + bRowOff[njp] + ((unsigned)kb ^ bXor[njp]));
#pragma unroll
      for (int mi = 0; mi < 2; mi++)
#pragma unroll
        for (int njp = 0; njp < 4; njp++) {
          mma16816(acc[mi][2 * njp],     af[mi], bf[njp][0], bf[njp][2]);
          mma16816(acc[mi][2 * njp + 1], af[mi], bf[njp][1], bf[njp][3]);
        }
    }

    // epilogue: rm[b] = min(rm[b], A[b][f] + d) over this chunk's 2 columns/row
    const float* As = (const float*)(sm + SM_A + buf * A_BUF);
#pragma unroll
    for (int nj = 0; nj < 8; nj++) {
      const int c0 = 64 * wf + 8 * nj + 2 * tl;
      float4 A0a = *(const float4*)(As + c0 * 8);        // col c0,  b0..3
      float4 A0b = *(const float4*)(As + c0 * 8 + 4);    // col c0,  b4..7
      float4 A1a = *(const float4*)(As + c0 * 8 + 8);    // col c0+1,b0..3
      float4 A1b = *(const float4*)(As + c0 * 8 + 12);   // col c0+1,b4..7
#pragma unroll
      for (int mi = 0; mi < 2; mi++) {
        const float* d = acc[mi][nj];
#pragma unroll
        for (int h = 0; h < 2; h++) {
          const float d0 = d[h * 2], d1 = d[h * 2 + 1];
          float* r = rm[mi][h];
          r[0] = fminf(r[0], fminf(A0a.x + d0, A1a.x + d1));
          r[1] = fminf(r[1], fminf(A0a.y + d0, A1a.y + d1));
          r[2] = fminf(r[2], fminf(A0a.z + d0, A1a.z + d1));
          r[3] = fminf(r[3], fminf(A0a.w + d0, A1a.w + d1));
          r[4] = fminf(r[4], fminf(A0b.x + d0, A1b.x + d1));
          r[5] = fminf(r[5], fminf(A0b.y + d0, A1b.y + d1));
          r[6] = fminf(r[6], fminf(A0b.z + d0, A1b.z + d1));
          r[7] = fminf(r[7], fminf(A0b.w + d0, A1b.w + d1));
        }
      }
    }
  }

  // reduce across the 4 tl lanes sharing each row, then atomics
#pragma unroll
  for (int mi = 0; mi < 2; mi++)
#pragma unroll
    for (int h = 0; h < 2; h++)
#pragma unroll
      for (int b = 0; b < BB; b++) {
        float v = rm[mi][h][b];
        v = fminf(v, __shfl_xor_sync(0xffffffffu, v, 1));
        v = fminf(v, __shfl_xor_sync(0xffffffffu, v, 2));
        rm[mi][h][b] = v;
      }
  if (tl == 0) {
#pragma unroll
    for (int mi = 0; mi < 2; mi++)
#pragma unroll
      for (int h = 0; h < 2; h++) {
        int n = n0 + 32 * wn + 16 * mi + 8 * h + g;
        if (n < N) {
#pragma unroll
          for (int b = 0; b < BB; b++)
            atomicMinF(&g_min[z][b][n], rm[mi][h][b]);
        }
      }
  }
}

// ---- finalize ----
__global__ void k_final(float* __restrict__ out, int N) {
  int idx = blockIdx.x * blockDim.x + threadIdx.x;
  if (idx >= 2 * BB * N) return;
  int z = idx / (BB * N);
  int r = idx - z * (BB * N);
  int b = r / N;
  int n = r - b * N;
  float d2 = g_min[z][b][n] + g_e2[n];
  d2 = fmaxf(d2, 0.f);
  out[idx] = expf(-0.5f * d2);
}

// ---------------------------------------------------------------------------
extern "C" void kernel_launch(void* const* d_in, const int* in_sizes, int n_in,
                              void* d_out, int out_size) {
  const float* rel = (const float*)d_in[0];
  const float* a1  = (const float*)d_in[1];
  const float* a2  = (const float*)d_in[2];
  const float* fr  = (const float*)d_in[3];
  const float* f1  = (const float*)d_in[4];
  const float* f2  = (const float*)d_in[5];
  const float* ent = (const float*)d_in[6];
  int F = in_sizes[3] / EE;
  int N = in_sizes[6] / EE;

  cudaFuncSetAttribute(k_main, cudaFuncAttributeMaxDynamicSharedMemorySize, SM_TOTAL);

  k_init<<<(2 * BB * FPAD) / 256, 256>>>();
  dim3 cgrid((FPAD * KROW) / 256, 3);
  k_conv<<<cgrid, 256>>>(ent, f2, f1, N, F);
  k_prepA<<<FPAD / 128, 128>>>(rel, a1, a2, fr, f1, f2, F);
  k_e2<<<(N + 127) / 128, 128>>>((const float4*)ent, N);

  int ntiles = FPAD / NTILE;   // 32 (padded rows are zeros; atomics guarded)
  dim3 grid(ntiles, FSPLIT, 2);
  k_main<<<grid, 256, SM_TOTAL>>>(N);

  int tot = 2 * BB * N;
  k_final<<<(tot + 255) / 256, 256>>>((float*)d_out, N);
}

// round 5
// speedup vs baseline: 3.3618x; 1.2599x over previous
#include <cuda_runtime.h>
#include <cuda_bf16.h>
#include <math_constants.h>
#include <cstdint>

#define BB 8
#define EE 100
#define FPAD 4096
#define NTILE 128         // n rows per CTA tile
#define FCH 128           // f cols per chunk
#define FSPLIT 2
#define KROW 128          // bf16 per stored row (256B), zeros past 99
#define NKS 7             // 7 x k16 = 112 (zeros past 99 contribute 0)

// smem layout
#define TILE_HALF 16384                 // 128 rows x 128B (one 64-wide bf16 half)
#define SM_ENT 0                        // 2 halves
#define SM_FACT (2*TILE_HALF)           // 2 buffers x 2 halves
#define FACT_BUF (2*TILE_HALF)
#define SM_A (SM_FACT + 2*FACT_BUF)     // 2 buffers of [128 f][8 b] bf16
#define A_BUF 2048
#define SM_TOTAL (SM_A + 2*A_BUF)       // 102400 B

// ---- device scratch ----
__device__ __nv_bfloat16 g_Ab[2][FPAD][BB];    // A transposed (bf16), +INF for f>=F
__device__ float g_e2[FPAD];
__device__ float g_min[2][BB][FPAD];
__device__ __nv_bfloat16 g_eb[FPAD * KROW];    // -2*ent
__device__ __nv_bfloat16 g_fb[2][FPAD * KROW]; // [0]=fa2(sp), [1]=fa1(po)

// ---- helpers ----
__device__ __forceinline__ unsigned swz(unsigned b) { return b ^ ((b >> 3) & 0x70); }
__device__ __forceinline__ unsigned smem_u32(const void* p) {
  return (unsigned)__cvta_generic_to_shared(p);
}
__device__ __forceinline__ void cp16(unsigned dst, const void* src) {
  asm volatile("cp.async.cg.shared.global [%0], [%1], 16;" :: "r"(dst), "l"(src));
}
__device__ __forceinline__ void ldmx4(uint32_t* r, unsigned addr) {
  asm volatile("ldmatrix.sync.aligned.m8n8.x4.shared.b16 {%0,%1,%2,%3}, [%4];"
               : "=r"(r[0]), "=r"(r[1]), "=r"(r[2]), "=r"(r[3]) : "r"(addr));
}
__device__ __forceinline__ void mma16816(float* c, const uint32_t* a,
                                         uint32_t b0, uint32_t b1) {
  asm volatile("mma.sync.aligned.m16n8k16.row.col.f32.bf16.bf16.f32 "
               "{%0,%1,%2,%3}, {%4,%5,%6,%7}, {%8,%9}, {%0,%1,%2,%3};"
               : "+f"(c[0]), "+f"(c[1]), "+f"(c[2]), "+f"(c[3])
               : "r"(a[0]), "r"(a[1]), "r"(a[2]), "r"(a[3]), "r"(b0), "r"(b1));
}
__device__ __forceinline__ uint32_t bcvt2(float x) {
  uint32_t r; asm("cvt.rn.bf16x2.f32 %0, %1, %1;" : "=r"(r) : "f"(x)); return r;
}
__device__ __forceinline__ uint32_t addbf2(uint32_t a, uint32_t b) {
  uint32_t r; asm("add.rn.bf16x2 %0, %1, %2;" : "=r"(r) : "r"(a), "r"(b)); return r;
}
__device__ __forceinline__ uint32_t minbf2(uint32_t a, uint32_t b) {
  uint32_t r; asm("min.bf16x2 %0, %1, %2;" : "=r"(r) : "r"(a), "r"(b)); return r;
}
__device__ __forceinline__ void atomicMinF(float* addr, float v) {
  if (v >= 0.0f) atomicMin((int*)addr, __float_as_int(v));
  else           atomicMax((unsigned int*)addr, __float_as_uint(v));
}

// ---- fused prep kernel: blockIdx.y selects task ----
//  sel 0: prepA (heavy, scheduled first)   blocks 0..15
//  sel 1: e2                               blocks 0..15
//  sel 2/3/4: bf16 convert ent/f2/f1       blocks 0..2047
//  sel 5: init g_min                       blocks 0..255
__global__ void k_prep(const float* __restrict__ rel, const float* __restrict__ a1,
                       const float* __restrict__ a2, const float* __restrict__ fr,
                       const float* __restrict__ f1, const float* __restrict__ f2,
                       const float* __restrict__ ent, int N, int F) {
  const int sel = blockIdx.y;
  const int tid = threadIdx.x;

  if (sel == 0) {
    if (blockIdx.x >= FPAD / 256) return;
    __shared__ __align__(16) float q[3][BB][EE];
    for (int i = tid; i < 3 * BB * EE; i += 256) {
      int t = i / (BB * EE), rem = i - t * (BB * EE);
      int b = rem / EE, e = rem - b * EE;
      const float* s = (t == 0) ? rel : (t == 1 ? a1 : a2);
      q[t][b][e] = s[b * EE + e];
    }
    __syncthreads();
    int f = blockIdx.x * 256 + tid;
    if (f >= F) {
#pragma unroll
      for (int b = 0; b < BB; b++) {
        g_Ab[0][f][b] = __float2bfloat16(CUDART_INF_F);
        g_Ab[1][f][b] = __float2bfloat16(CUDART_INF_F);
      }
      return;
    }
    const float4* pr = (const float4*)(fr + (size_t)f * EE);
    const float4* p1 = (const float4*)(f1 + (size_t)f * EE);
    const float4* p2 = (const float4*)(f2 + (size_t)f * EE);
    float sr[BB], s1v[BB], s2v[BB];
#pragma unroll
    for (int b = 0; b < BB; b++) { sr[b] = 0.f; s1v[b] = 0.f; s2v[b] = 0.f; }
    float n1 = 0.f, n2 = 0.f;
    for (int e4 = 0; e4 < EE / 4; e4++) {
      float4 vr = pr[e4], v1 = p1[e4], v2 = p2[e4];
      n1 += v1.x * v1.x + v1.y * v1.y + v1.z * v1.z + v1.w * v1.w;
      n2 += v2.x * v2.x + v2.y * v2.y + v2.z * v2.z + v2.w * v2.w;
#pragma unroll
      for (int b = 0; b < BB; b++) {
        float4 qr = *(const float4*)&q[0][b][e4 * 4];
        float4 q1 = *(const float4*)&q[1][b][e4 * 4];
        float4 q2 = *(const float4*)&q[2][b][e4 * 4];
        float t;
        t = qr.x - vr.x; sr[b] += t * t;  t = qr.y - vr.y; sr[b] += t * t;
        t = qr.z - vr.z; sr[b] += t * t;  t = qr.w - vr.w; sr[b] += t * t;
        t = q1.x - v1.x; s1v[b] += t * t; t = q1.y - v1.y; s1v[b] += t * t;
        t = q1.z - v1.z; s1v[b] += t * t; t = q1.w - v1.w; s1v[b] += t * t;
        t = q2.x - v2.x; s2v[b] += t * t; t = q2.y - v2.y; s2v[b] += t * t;
        t = q2.z - v2.z; s2v[b] += t * t; t = q2.w - v2.w; s2v[b] += t * t;
      }
    }
#pragma unroll
    for (int b = 0; b < BB; b++) {
      g_Ab[0][f][b] = __float2bfloat16(sr[b] + s1v[b] + n2);  // sp pairs with fa2
      g_Ab[1][f][b] = __float2bfloat16(sr[b] + s2v[b] + n1);  // po pairs with fa1
    }
  } else if (sel == 1) {
    if (blockIdx.x >= FPAD / 256) return;
    int n = blockIdx.x * 256 + tid;
    if (n >= N) return;
    const float4* e4p = (const float4*)ent;
    float s = 0.f;
#pragma unroll
    for (int qq = 0; qq < EE / 4; qq++) {
      float4 v = e4p[n * (EE / 4) + qq];
      s += v.x * v.x + v.y * v.y + v.z * v.z + v.w * v.w;
    }
    g_e2[n] = s;
  } else if (sel <= 4) {
    int idx = blockIdx.x * 256 + tid;
    int r = idx >> 7, j = idx & 127;
    const float* src = (sel == 2) ? ent : (sel == 3 ? f2 : f1);
    int rows = (sel == 2) ? N : F;
    float scale = (sel == 2) ? -2.0f : 1.0f;
    float v = (r < rows && j < EE) ? scale * src[r * EE + j] : 0.f;
    __nv_bfloat16* dst = (sel == 2) ? g_eb : g_fb[sel - 3];
    dst[idx] = __float2bfloat16(v);
  } else {
    int i = blockIdx.x * 256 + tid;
    if (i < 2 * BB * FPAD) ((float*)g_min)[i] = CUDART_INF_F;
  }
}

// ---- main HMMA kernel ----
__global__ __launch_bounds__(256, 1) void k_main(int N) {
  extern __shared__ char sm[];
  const int tid = threadIdx.x;
  const int wid = tid >> 5;
  const int lane = tid & 31;
  const unsigned smb = smem_u32(sm);
  const int z = blockIdx.z;
  const int n0 = blockIdx.x * NTILE;
  const int f0base = blockIdx.y * (FPAD / FSPLIT);
  const int NCH = (FPAD / FSPLIT) / FCH;   // 16
  const __nv_bfloat16* fb = g_fb[z];

  const int wn = wid & 3, wf = wid >> 2;   // warp grid 4(n) x 2(f)
  const int g = lane >> 2, tl = lane & 3;
  const int lrow = lane & 7, mm = lane >> 3;

  // ldmatrix per-lane bases
  const int xoff = 16 * (mm >> 1);
  unsigned aRowOff[2], aXor[2];
#pragma unroll
  for (int mi = 0; mi < 2; mi++) {
    int r = 32 * wn + 16 * mi + lrow + 8 * (mm & 1);
    aRowOff[mi] = r * 128;
    aXor[mi] = (r & 7) * 16;
  }
  unsigned bRowOff[4], bXor[4];
#pragma unroll
  for (int njp = 0; njp < 4; njp++) {
    int r = 64 * wf + 16 * njp + lrow + 8 * (mm & 1);
    bRowOff[njp] = r * 128;
    bXor[njp] = (r & 7) * 16;
  }

  // staging helpers
  auto stage_tile = [&](const __nv_bfloat16* srcRows, unsigned dstBase) {
    const char* sb = (const char*)srcRows;
#pragma unroll
    for (int i = 0; i < 8; i++) {
      int idx = tid + i * 256;
      int half = idx >> 10;
      int rem = idx & 1023;
      int r = rem >> 3, gg = rem & 7;
      cp16(dstBase + half * TILE_HALF + swz(r * 128 + gg * 16),
           sb + (size_t)r * 256 + half * 128 + gg * 16);
    }
  };
  auto stage_fact = [&](int c, int bi) {
    stage_tile(fb + (size_t)(f0base + c * FCH) * KROW, smb + SM_FACT + bi * FACT_BUF);
  };
  auto stage_A = [&](int c, int bi) {
    if (tid < FCH) {
      int f0 = f0base + c * FCH;
      cp16(smb + SM_A + bi * A_BUF + tid * 16, &g_Ab[z][f0 + tid][0]);
    }
  };

  stage_tile(g_eb + (size_t)n0 * KROW, smb + SM_ENT);
  stage_fact(0, 0);
  stage_A(0, 0);
  asm volatile("cp.async.commit_group;");

  uint32_t rmP[2][2][4];   // [mi][rowhalf][b-pair], bf16x2, init +INF|+INF
#pragma unroll
  for (int mi = 0; mi < 2; mi++)
#pragma unroll
    for (int h = 0; h < 2; h++)
#pragma unroll
      for (int j = 0; j < 4; j++) rmP[mi][h][j] = 0x7F807F80u;

  for (int c = 0; c < NCH; c++) {
    const int buf = c & 1;
    asm volatile("cp.async.wait_group 0;");
    __syncthreads();
    if (c + 1 < NCH) {
      stage_fact(c + 1, buf ^ 1);
      stage_A(c + 1, buf ^ 1);
      asm volatile("cp.async.commit_group;");
    }

    float acc[2][8][4];
#pragma unroll
    for (int mi = 0; mi < 2; mi++)
#pragma unroll
      for (int nj = 0; nj < 8; nj++)
#pragma unroll
        for (int k = 0; k < 4; k++) acc[mi][nj][k] = 0.f;

    const unsigned fBase = smb + SM_FACT + buf * FACT_BUF;
#pragma unroll
    for (int ks = 0; ks < NKS; ks++) {
      const int half = (ks >= 4);
      const int kb = (ks - (half ? 4 : 0)) * 32 + xoff;
      const unsigned aB = smb + SM_ENT + half * TILE_HALF;
      const unsigned bB = fBase + half * TILE_HALF;
      uint32_t af[2][4];
#pragma unroll
      for (int mi = 0; mi < 2; mi++)
        ldmx4(af[mi], aB + aRowOff[mi] + ((unsigned)kb ^ aXor[mi]));
      uint32_t bf[4][4];
#pragma unroll
      for (int njp = 0; njp < 4; njp++)
        ldmx4(bf[njp], bB + bRowOff[njp] + ((unsigned)kb ^ bXor[njp]));
#pragma unroll
      for (int mi = 0; mi < 2; mi++)
#pragma unroll
        for (int njp = 0; njp < 4; njp++) {
          mma16816(acc[mi][2 * njp],     af[mi], bf[njp][0], bf[njp][2]);
          mma16816(acc[mi][2 * njp + 1], af[mi], bf[njp][1], bf[njp][3]);
        }
    }

    // packed bf16x2 epilogue: rm = min(rm, A + d)
    const uint32_t* As = (const uint32_t*)(sm + SM_A + buf * A_BUF);
#pragma unroll
    for (int nj = 0; nj < 8; nj++) {
      const int c0 = 64 * wf + 8 * nj + 2 * tl;
      uint4 A0 = *(const uint4*)(As + c0 * 4);       // col c0:  b0..7 (4 bf16x2)
      uint4 A1 = *(const uint4*)(As + c0 * 4 + 4);   // col c0+1
#pragma unroll
      for (int mi = 0; mi < 2; mi++) {
        const float* d = acc[mi][nj];
#pragma unroll
        for (int h = 0; h < 2; h++) {
          uint32_t d0 = bcvt2(d[h * 2]);
          uint32_t d1 = bcvt2(d[h * 2 + 1]);
          uint32_t* r = rmP[mi][h];
          r[0] = minbf2(r[0], minbf2(addbf2(A0.x, d0), addbf2(A1.x, d1)));
          r[1] = minbf2(r[1], minbf2(addbf2(A0.y, d0), addbf2(A1.y, d1)));
          r[2] = minbf2(r[2], minbf2(addbf2(A0.z, d0), addbf2(A1.z, d1)));
          r[3] = minbf2(r[3], minbf2(addbf2(A0.w, d0), addbf2(A1.w, d1)));
        }
      }
    }
  }

  // reduce across the 4 tl lanes sharing each row, then atomics
#pragma unroll
  for (int mi = 0; mi < 2; mi++)
#pragma unroll
    for (int h = 0; h < 2; h++)
#pragma unroll
      for (int j = 0; j < 4; j++) {
        uint32_t v = rmP[mi][h][j];
        v = minbf2(v, __shfl_xor_sync(0xffffffffu, v, 1));
        v = minbf2(v, __shfl_xor_sync(0xffffffffu, v, 2));
        rmP[mi][h][j] = v;
      }
  if (tl == 0) {
#pragma unroll
    for (int mi = 0; mi < 2; mi++)
#pragma unroll
      for (int h = 0; h < 2; h++) {
        int n = n0 + 32 * wn + 16 * mi + 8 * h + g;
        if (n < N) {
#pragma unroll
          for (int j = 0; j < 4; j++) {
            uint32_t v = rmP[mi][h][j];
            float lo = __uint_as_float((v & 0xFFFFu) << 16);
            float hi = __uint_as_float(v & 0xFFFF0000u);
            atomicMinF(&g_min[z][2 * j][n], lo);
            atomicMinF(&g_min[z][2 * j + 1][n], hi);
          }
        }
      }
  }
}

// ---- finalize ----
__global__ void k_final(float* __restrict__ out, int N) {
  int idx = blockIdx.x * blockDim.x + threadIdx.x;
  if (idx >= 2 * BB * N) return;
  int z = idx / (BB * N);
  int r = idx - z * (BB * N);
  int b = r / N;
  int n = r - b * N;
  float d2 = g_min[z][b][n] + g_e2[n];
  d2 = fmaxf(d2, 0.f);
  out[idx] = expf(-0.5f * d2);
}

// ---------------------------------------------------------------------------
extern "C" void kernel_launch(void* const* d_in, const int* in_sizes, int n_in,
                              void* d_out, int out_size) {
  const float* rel = (const float*)d_in[0];
  const float* a1  = (const float*)d_in[1];
  const float* a2  = (const float*)d_in[2];
  const float* fr  = (const float*)d_in[3];
  const float* f1  = (const float*)d_in[4];
  const float* f2  = (const float*)d_in[5];
  const float* ent = (const float*)d_in[6];
  int F = in_sizes[3] / EE;
  int N = in_sizes[6] / EE;

  cudaFuncSetAttribute(k_main, cudaFuncAttributeMaxDynamicSharedMemorySize, SM_TOTAL);

  dim3 pgrid((FPAD * KROW) / 256, 6);     // 2048 x 6; heavy branch = sel 0, first
  k_prep<<<pgrid, 256>>>(rel, a1, a2, fr, f1, f2, ent, N, F);

  dim3 grid(FPAD / NTILE, FSPLIT, 2);     // 32 x 2 x 2 = 128 CTAs, one wave
  k_main<<<grid, 256, SM_TOTAL>>>(N);

  int tot = 2 * BB * N;
  k_final<<<(tot + 255) / 256, 256>>>((float*)d_out, N);
}

// round 6
// speedup vs baseline: 3.6148x; 1.0753x over previous
#include <cuda_runtime.h>
#include <cuda_bf16.h>
#include <math_constants.h>
#include <cstdint>

#define BB 8
#define EE 100
#define FPAD 4096
#define NTILE 128         // n rows per CTA tile
#define FCH 128           // f cols per chunk
#define FSPLIT 2
#define KROW 128          // bf16 per stored row (256B), zeros past 99
#define NKS 7             // 7 x k16 = 112 (zeros past 99 contribute 0)

// smem layout
#define TILE_HALF 16384                 // 128 rows x 128B (one 64-wide bf16 half)
#define SM_ENT 0                        // 2 halves
#define SM_FACT (2*TILE_HALF)           // 2 buffers x 2 halves
#define FACT_BUF (2*TILE_HALF)
#define SM_A (SM_FACT + 2*FACT_BUF)     // 2 buffers of [128 f][8 b] bf16
#define A_BUF 2048
#define SM_TOTAL (SM_A + 2*A_BUF)       // 102400 B

// ---- device scratch ----
__device__ __nv_bfloat16 g_Ab[2][FPAD][BB];    // A transposed (bf16), +INF for f>=F
__device__ float g_e2[FPAD];
__device__ float g_min[2][BB][FPAD];
__device__ __nv_bfloat16 g_eb[FPAD * KROW];    // -2*ent
__device__ __nv_bfloat16 g_fb[2][FPAD * KROW]; // [0]=fa2(sp), [1]=fa1(po)
__device__ int g_cnt[2][FPAD / NTILE];         // arrival counters per (z, n-tile)

// ---- helpers ----
__device__ __forceinline__ unsigned swz(unsigned b) { return b ^ ((b >> 3) & 0x70); }
__device__ __forceinline__ unsigned smem_u32(const void* p) {
  return (unsigned)__cvta_generic_to_shared(p);
}
__device__ __forceinline__ void cp16(unsigned dst, const void* src) {
  asm volatile("cp.async.cg.shared.global [%0], [%1], 16;" :: "r"(dst), "l"(src));
}
__device__ __forceinline__ void ldmx4(uint32_t* r, unsigned addr) {
  asm volatile("ldmatrix.sync.aligned.m8n8.x4.shared.b16 {%0,%1,%2,%3}, [%4];"
               : "=r"(r[0]), "=r"(r[1]), "=r"(r[2]), "=r"(r[3]) : "r"(addr));
}
__device__ __forceinline__ void mma16816(float* c, const uint32_t* a,
                                         uint32_t b0, uint32_t b1) {
  asm volatile("mma.sync.aligned.m16n8k16.row.col.f32.bf16.bf16.f32 "
               "{%0,%1,%2,%3}, {%4,%5,%6,%7}, {%8,%9}, {%0,%1,%2,%3};"
               : "+f"(c[0]), "+f"(c[1]), "+f"(c[2]), "+f"(c[3])
               : "r"(a[0]), "r"(a[1]), "r"(a[2]), "r"(a[3]), "r"(b0), "r"(b1));
}
__device__ __forceinline__ uint32_t bcvt2(float x) {
  uint32_t r; asm("cvt.rn.bf16x2.f32 %0, %1, %1;" : "=r"(r) : "f"(x)); return r;
}
__device__ __forceinline__ uint32_t addbf2(uint32_t a, uint32_t b) {
  uint32_t r; asm("add.rn.bf16x2 %0, %1, %2;" : "=r"(r) : "r"(a), "r"(b)); return r;
}
__device__ __forceinline__ uint32_t minbf2(uint32_t a, uint32_t b) {
  uint32_t r; asm("min.bf16x2 %0, %1, %2;" : "=r"(r) : "r"(a), "r"(b)); return r;
}
__device__ __forceinline__ void atomicMinF(float* addr, float v) {
  if (v >= 0.0f) atomicMin((int*)addr, __float_as_int(v));
  else           atomicMax((unsigned int*)addr, __float_as_uint(v));
}

// ---- fused prep kernel: blockIdx.y selects task ----
//  sel 0: prepA, one thread per (f,b)      blocks 0..127
//  sel 1: e2                               blocks 0..15
//  sel 2/3/4: bf16 convert ent/f2/f1       blocks 0..2047
//  sel 5: init g_min + counters            blocks 0..255
__global__ void k_prep(const float* __restrict__ rel, const float* __restrict__ a1,
                       const float* __restrict__ a2, const float* __restrict__ fr,
                       const float* __restrict__ f1, const float* __restrict__ f2,
                       const float* __restrict__ ent, int N, int F) {
  const int sel = blockIdx.y;
  const int tid = threadIdx.x;

  if (sel == 0) {
    if (blockIdx.x >= (FPAD * BB) / 256) return;
    __shared__ __align__(16) float q[3][BB][EE];
    for (int i = tid; i < 3 * BB * EE; i += 256) {
      int t = i / (BB * EE), rem = i - t * (BB * EE);
      int b = rem / EE, e = rem - b * EE;
      const float* s = (t == 0) ? rel : (t == 1 ? a1 : a2);
      q[t][b][e] = s[b * EE + e];
    }
    __syncthreads();
    int idx = blockIdx.x * 256 + tid;
    int f = idx >> 3, b = idx & 7;
    if (f >= F) {
      g_Ab[0][f][b] = __float2bfloat16(CUDART_INF_F);
      g_Ab[1][f][b] = __float2bfloat16(CUDART_INF_F);
      return;
    }
    const float4* pr = (const float4*)(fr + (size_t)f * EE);
    const float4* p1 = (const float4*)(f1 + (size_t)f * EE);
    const float4* p2 = (const float4*)(f2 + (size_t)f * EE);
    float sr = 0.f, s1v = 0.f, s2v = 0.f, n1 = 0.f, n2 = 0.f;
#pragma unroll 5
    for (int e4 = 0; e4 < EE / 4; e4++) {
      float4 vr = pr[e4], v1 = p1[e4], v2 = p2[e4];
      n1 += v1.x * v1.x + v1.y * v1.y + v1.z * v1.z + v1.w * v1.w;
      n2 += v2.x * v2.x + v2.y * v2.y + v2.z * v2.z + v2.w * v2.w;
      float4 qr = *(const float4*)&q[0][b][e4 * 4];
      float4 q1 = *(const float4*)&q[1][b][e4 * 4];
      float4 q2 = *(const float4*)&q[2][b][e4 * 4];
      float t;
      t = qr.x - vr.x; sr += t * t;  t = qr.y - vr.y; sr += t * t;
      t = qr.z - vr.z; sr += t * t;  t = qr.w - vr.w; sr += t * t;
      t = q1.x - v1.x; s1v += t * t; t = q1.y - v1.y; s1v += t * t;
      t = q1.z - v1.z; s1v += t * t; t = q1.w - v1.w; s1v += t * t;
      t = q2.x - v2.x; s2v += t * t; t = q2.y - v2.y; s2v += t * t;
      t = q2.z - v2.z; s2v += t * t; t = q2.w - v2.w; s2v += t * t;
    }
    g_Ab[0][f][b] = __float2bfloat16(sr + s1v + n2);  // sp pairs with fa2
    g_Ab[1][f][b] = __float2bfloat16(sr + s2v + n1);  // po pairs with fa1
  } else if (sel == 1) {
    if (blockIdx.x >= FPAD / 256) return;
    int n = blockIdx.x * 256 + tid;
    if (n >= N) return;
    const float4* e4p = (const float4*)ent;
    float s = 0.f;
#pragma unroll
    for (int qq = 0; qq < EE / 4; qq++) {
      float4 v = e4p[n * (EE / 4) + qq];
      s += v.x * v.x + v.y * v.y + v.z * v.z + v.w * v.w;
    }
    g_e2[n] = s;
  } else if (sel <= 4) {
    int idx = blockIdx.x * 256 + tid;
    int r = idx >> 7, j = idx & 127;
    const float* src = (sel == 2) ? ent : (sel == 3 ? f2 : f1);
    int rows = (sel == 2) ? N : F;
    float scale = (sel == 2) ? -2.0f : 1.0f;
    float v = (r < rows && j < EE) ? scale * src[r * EE + j] : 0.f;
    __nv_bfloat16* dst = (sel == 2) ? g_eb : g_fb[sel - 3];
    dst[idx] = __float2bfloat16(v);
  } else {
    int i = blockIdx.x * 256 + tid;
    if (i < 2 * BB * FPAD) ((float*)g_min)[i] = CUDART_INF_F;
    if (i < 2 * (FPAD / NTILE)) ((int*)g_cnt)[i] = 0;
  }
}

// ---- main HMMA kernel (finalize fused via arrival counters) ----
__global__ __launch_bounds__(256, 1) void k_main(float* __restrict__ out, int N) {
  extern __shared__ char sm[];
  const int tid = threadIdx.x;
  const int wid = tid >> 5;
  const int lane = tid & 31;
  const unsigned smb = smem_u32(sm);
  const int z = blockIdx.z;
  const int n0 = blockIdx.x * NTILE;
  const int f0base = blockIdx.y * (FPAD / FSPLIT);
  const int NCH = (FPAD / FSPLIT) / FCH;   // 16
  const __nv_bfloat16* fb = g_fb[z];

  const int wn = wid & 3, wf = wid >> 2;   // warp grid 4(n) x 2(f)
  const int g = lane >> 2, tl = lane & 3;
  const int lrow = lane & 7, mm = lane >> 3;

  // ldmatrix per-lane bases
  const int xoff = 16 * (mm >> 1);
  unsigned aRowOff[2], aXor[2];
#pragma unroll
  for (int mi = 0; mi < 2; mi++) {
    int r = 32 * wn + 16 * mi + lrow + 8 * (mm & 1);
    aRowOff[mi] = r * 128;
    aXor[mi] = (r & 7) * 16;
  }
  unsigned bRowOff[4], bXor[4];
#pragma unroll
  for (int njp = 0; njp < 4; njp++) {
    int r = 64 * wf + 16 * njp + lrow + 8 * (mm & 1);
    bRowOff[njp] = r * 128;
    bXor[njp] = (r & 7) * 16;
  }

  // staging helpers
  auto stage_tile = [&](const __nv_bfloat16* srcRows, unsigned dstBase) {
    const char* sb = (const char*)srcRows;
#pragma unroll
    for (int i = 0; i < 8; i++) {
      int idx = tid + i * 256;
      int half = idx >> 10;
      int rem = idx & 1023;
      int r = rem >> 3, gg = rem & 7;
      cp16(dstBase + half * TILE_HALF + swz(r * 128 + gg * 16),
           sb + (size_t)r * 256 + half * 128 + gg * 16);
    }
  };
  auto stage_fact = [&](int c, int bi) {
    stage_tile(fb + (size_t)(f0base + c * FCH) * KROW, smb + SM_FACT + bi * FACT_BUF);
  };
  auto stage_A = [&](int c, int bi) {
    if (tid < FCH) {
      int f0 = f0base + c * FCH;
      cp16(smb + SM_A + bi * A_BUF + tid * 16, &g_Ab[z][f0 + tid][0]);
    }
  };

  stage_tile(g_eb + (size_t)n0 * KROW, smb + SM_ENT);
  stage_fact(0, 0);
  stage_A(0, 0);
  asm volatile("cp.async.commit_group;");

  uint32_t rmP[2][2][4];   // [mi][rowhalf][b-pair], bf16x2, init +INF|+INF
#pragma unroll
  for (int mi = 0; mi < 2; mi++)
#pragma unroll
    for (int h = 0; h < 2; h++)
#pragma unroll
      for (int j = 0; j < 4; j++) rmP[mi][h][j] = 0x7F807F80u;

  for (int c = 0; c < NCH; c++) {
    const int buf = c & 1;
    asm volatile("cp.async.wait_group 0;");
    __syncthreads();
    if (c + 1 < NCH) {
      stage_fact(c + 1, buf ^ 1);
      stage_A(c + 1, buf ^ 1);
      asm volatile("cp.async.commit_group;");
    }

    float acc[2][8][4];
#pragma unroll
    for (int mi = 0; mi < 2; mi++)
#pragma unroll
      for (int nj = 0; nj < 8; nj++)
#pragma unroll
        for (int k = 0; k < 4; k++) acc[mi][nj][k] = 0.f;

    const unsigned fBase = smb + SM_FACT + buf * FACT_BUF;
#pragma unroll
    for (int ks = 0; ks < NKS; ks++) {
      const int half = (ks >= 4);
      const int kb = (ks - (half ? 4 : 0)) * 32 + xoff;
      const unsigned aB = smb + SM_ENT + half * TILE_HALF;
      const unsigned bB = fBase + half * TILE_HALF;
      uint32_t af[2][4];
#pragma unroll
      for (int mi = 0; mi < 2; mi++)
        ldmx4(af[mi], aB + aRowOff[mi] + ((unsigned)kb ^ aXor[mi]));
      uint32_t bf[4][4];
#pragma unroll
      for (int njp = 0; njp < 4; njp++)
        ldmx4(bf[njp], bB + bRowOff[njp] + ((unsigned)kb ^ bXor[njp]));
#pragma unroll
      for (int mi = 0; mi < 2; mi++)
#pragma unroll
        for (int njp = 0; njp < 4; njp++) {
          mma16816(acc[mi][2 * njp],     af[mi], bf[njp][0], bf[njp][2]);
          mma16816(acc[mi][2 * njp + 1], af[mi], bf[njp][1], bf[njp][3]);
        }
    }

    // packed bf16x2 epilogue: rm = min(rm, A + d)
    const uint32_t* As = (const uint32_t*)(sm + SM_A + buf * A_BUF);
#pragma unroll
    for (int nj = 0; nj < 8; nj++) {
      const int c0 = 64 * wf + 8 * nj + 2 * tl;
      uint4 A0 = *(const uint4*)(As + c0 * 4);       // col c0:  b0..7 (4 bf16x2)
      uint4 A1 = *(const uint4*)(As + c0 * 4 + 4);   // col c0+1
#pragma unroll
      for (int mi = 0; mi < 2; mi++) {
        const float* d = acc[mi][nj];
#pragma unroll
        for (int h = 0; h < 2; h++) {
          uint32_t d0 = bcvt2(d[h * 2]);
          uint32_t d1 = bcvt2(d[h * 2 + 1]);
          uint32_t* r = rmP[mi][h];
          r[0] = minbf2(r[0], minbf2(addbf2(A0.x, d0), addbf2(A1.x, d1)));
          r[1] = minbf2(r[1], minbf2(addbf2(A0.y, d0), addbf2(A1.y, d1)));
          r[2] = minbf2(r[2], minbf2(addbf2(A0.z, d0), addbf2(A1.z, d1)));
          r[3] = minbf2(r[3], minbf2(addbf2(A0.w, d0), addbf2(A1.w, d1)));
        }
      }
    }
  }

  // reduce across the 4 tl lanes sharing each row, then atomics
#pragma unroll
  for (int mi = 0; mi < 2; mi++)
#pragma unroll
    for (int h = 0; h < 2; h++)
#pragma unroll
      for (int j = 0; j < 4; j++) {
        uint32_t v = rmP[mi][h][j];
        v = minbf2(v, __shfl_xor_sync(0xffffffffu, v, 1));
        v = minbf2(v, __shfl_xor_sync(0xffffffffu, v, 2));
        rmP[mi][h][j] = v;
      }
  if (tl == 0) {
#pragma unroll
    for (int mi = 0; mi < 2; mi++)
#pragma unroll
      for (int h = 0; h < 2; h++) {
        int n = n0 + 32 * wn + 16 * mi + 8 * h + g;
        if (n < N) {
#pragma unroll
          for (int j = 0; j < 4; j++) {
            uint32_t v = rmP[mi][h][j];
            float lo = __uint_as_float((v & 0xFFFFu) << 16);
            float hi = __uint_as_float(v & 0xFFFF0000u);
            atomicMinF(&g_min[z][2 * j][n], lo);
            atomicMinF(&g_min[z][2 * j + 1][n], hi);
          }
        }
      }
  }

  // fused finalize: last CTA for this (z, n-tile) writes the outputs
  __shared__ int s_last;
  __threadfence();
  __syncthreads();
  if (tid == 0)
    s_last = atomicAdd(&g_cnt[z][blockIdx.x], 1);
  __syncthreads();
  if (s_last == FSPLIT - 1) {
    __threadfence();
    for (int o = tid; o < BB * NTILE; o += 256) {
      int b = o >> 7, nl = o & 127;
      int n = n0 + nl;
      if (n < N) {
        float d2 = fmaxf(g_min[z][b][n] + g_e2[n], 0.f);
        out[((size_t)z * BB + b) * N + n] = expf(-0.5f * d2);
      }
    }
  }
}

// ---------------------------------------------------------------------------
extern "C" void kernel_launch(void* const* d_in, const int* in_sizes, int n_in,
                              void* d_out, int out_size) {
  const float* rel = (const float*)d_in[0];
  const float* a1  = (const float*)d_in[1];
  const float* a2  = (const float*)d_in[2];
  const float* fr  = (const float*)d_in[3];
  const float* f1  = (const float*)d_in[4];
  const float* f2  = (const float*)d_in[5];
  const float* ent = (const float*)d_in[6];
  int F = in_sizes[3] / EE;
  int N = in_sizes[6] / EE;

  cudaFuncSetAttribute(k_main, cudaFuncAttributeMaxDynamicSharedMemorySize, SM_TOTAL);

  dim3 pgrid((FPAD * KROW) / 256, 6);     // 2048 x 6; heavy branch = sel 0, first
  k_prep<<<pgrid, 256>>>(rel, a1, a2, fr, f1, f2, ent, N, F);

  dim3 grid(FPAD / NTILE, FSPLIT, 2);     // 32 x 2 x 2 = 128 CTAs, one wave
  k_main<<<grid, 256, SM_TOTAL>>>((float*)d_out, N);
}